// round 16
// baseline (speedup 1.0000x reference)
#include <cuda_runtime.h>
#include <math.h>

// RecurrentAttention: B=128, S=8192, D=64
//   scores[b,s] = sum_d x[b,s,d] * v[d]
//   alpha[b,s]  = softmax_s(scores)
//   out[b,d]    = sum_s alpha[b,s] * x[b,s,d]
// Output layout: d_out[0..B*D) = out, d_out[B*D..) = alpha.
//
// Three kernels:
//  pass1 (unchanged, proven): 2048 CTAs x 256 thr, split-S C=16, online
//         softmax, raw scores -> alpha buffer, partials -> g_part.
//  merge: 128 CTAs x 64 thr. Per batch: merge 16 partials ONCE, write
//         out[b,:], store (M, invL) to g_stat.
//  xform: 512 CTAs x 256 thr. Pure stream: alpha = exp(s - M) * invL,
//         2 float4 per thread, per-batch stats via broadcast loads.

#define BB 128
#define SS 8192
#define DD 64
#define CC 16
#define ROWS_CTA (SS / CC)          // 512
#define T1 256
#define W1 (T1 / 32)                // 8 warps
#define RPW (ROWS_CTA / W1)         // 64 rows per warp
#define UU 8
#define PART_STRIDE 66              // m, l, acc[64]

__device__ float g_part[BB * CC * PART_STRIDE];
__device__ float g_stat[BB * 2];    // (M, invL) per batch

__global__ __launch_bounds__(T1, 6)
void ra_pass1(const float* __restrict__ x,
              const float* __restrict__ v,
              float* __restrict__ alpha)   // raw scores written here
{
    __shared__ float s_scores[ROWS_CTA];   // 2 KB
    __shared__ float s_m[W1];
    __shared__ float s_l[W1];
    __shared__ float s_f[W1];
    __shared__ float s_acc[W1 * DD];       // 2 KB

    const int bx    = blockIdx.x;
    const int b     = bx >> 4;             // / CC
    const int chunk = bx & 15;
    const int tid   = threadIdx.x;
    const int w     = tid >> 5;
    const int lane  = tid & 31;

    const float v0 = v[2 * lane];
    const float v1 = v[2 * lane + 1];

    const float2* xrow =
        reinterpret_cast<const float2*>(
            x + ((size_t)b * SS + (size_t)chunk * ROWS_CTA + (size_t)w * RPW) * DD) + lane;

    float m  = -3.0e38f;
    float l  = 0.0f;
    float a0 = 0.0f, a1 = 0.0f;

    const int score_base = w * RPW;

    for (int i = 0; i < RPW; i += UU) {
        float2 xv[UU];
        #pragma unroll
        for (int u = 0; u < UU; u++)
            xv[u] = xrow[(i + u) * (DD / 2)];

        #pragma unroll
        for (int u = 0; u < UU; u++) {
            float p = fmaf(xv[u].x, v0, xv[u].y * v1);
            p += __shfl_xor_sync(0xffffffffu, p, 16);
            p += __shfl_xor_sync(0xffffffffu, p, 8);
            p += __shfl_xor_sync(0xffffffffu, p, 4);
            p += __shfl_xor_sync(0xffffffffu, p, 2);
            p += __shfl_xor_sync(0xffffffffu, p, 1);

            if (lane == 0) s_scores[score_base + i + u] = p;

            // warp-uniform branch (p, m identical on all lanes)
            if (p <= m) {
                float wt = __expf(p - m);
                l += wt;
                a0 = fmaf(wt, xv[u].x, a0);
                a1 = fmaf(wt, xv[u].y, a1);
            } else {
                float corr = __expf(m - p);
                l  = fmaf(l,  corr, 1.0f);
                a0 = fmaf(a0, corr, xv[u].x);
                a1 = fmaf(a1, corr, xv[u].y);
                m  = p;
            }
        }
    }

    if (lane == 0) { s_m[w] = m; s_l[w] = l; }
    s_acc[w * DD + 2 * lane]     = a0;
    s_acc[w * DD + 2 * lane + 1] = a1;
    __syncthreads();

    float* part = g_part + (size_t)bx * PART_STRIDE;

    if (w == 0) {
        float mw = (lane < W1) ? s_m[lane] : -3.0e38f;
        float M  = mw;
        #pragma unroll
        for (int o = 16; o; o >>= 1) M = fmaxf(M, __shfl_xor_sync(0xffffffffu, M, o));
        float f  = __expf(mw - M);
        float lw = (lane < W1) ? s_l[lane] * f : 0.0f;
        #pragma unroll
        for (int o = 16; o; o >>= 1) lw += __shfl_xor_sync(0xffffffffu, lw, o);
        if (lane < W1) s_f[lane] = f;
        if (lane == 0) { part[0] = M; part[1] = lw; }
    }
    __syncthreads();

    if (tid < DD) {
        float acc = 0.0f;
        #pragma unroll
        for (int ww = 0; ww < W1; ww++)
            acc = fmaf(s_acc[ww * DD + tid], s_f[ww], acc);
        part[2 + tid] = acc;
    }

    if (tid < ROWS_CTA / 4) {
        float4 sc = reinterpret_cast<const float4*>(s_scores)[tid];
        reinterpret_cast<float4*>(
            alpha + (size_t)b * SS + (size_t)chunk * ROWS_CTA)[tid] = sc;
    }
}

// Merge 16 partials per batch once; write out[b,:] and (M, invL).
__global__ __launch_bounds__(64)
void ra_merge(float* __restrict__ out)
{
    __shared__ float s_f[CC];
    __shared__ float s_M, s_invL;

    const int b   = blockIdx.x;
    const int tid = threadIdx.x;
    const float* P = g_part + (size_t)(b * CC) * PART_STRIDE;

    if (tid < 32) {
        const int lane = tid;
        float mc = (lane < CC) ? P[lane * PART_STRIDE + 0] : -3.0e38f;
        float lc = (lane < CC) ? P[lane * PART_STRIDE + 1] : 0.0f;
        float M = mc;
        #pragma unroll
        for (int o = 16; o; o >>= 1) M = fmaxf(M, __shfl_xor_sync(0xffffffffu, M, o));
        float f = __expf(mc - M);
        float L = lc * f;
        #pragma unroll
        for (int o = 16; o; o >>= 1) L += __shfl_xor_sync(0xffffffffu, L, o);
        if (lane < CC) s_f[lane] = f;
        if (lane == 0) {
            float invL = 1.0f / L;
            s_M = M; s_invL = invL;
            g_stat[2 * b]     = M;
            g_stat[2 * b + 1] = invL;
        }
    }
    __syncthreads();

    // out[b,d], d = tid (64 threads)
    float acc = 0.0f;
    #pragma unroll
    for (int c = 0; c < CC; c++)
        acc = fmaf(P[c * PART_STRIDE + 2 + tid], s_f[c], acc);
    out[b * DD + tid] = acc * s_invL;
}

// Pure streaming transform: alpha = exp(score - M) * invL.
#define T3 256
#define V3 2    // float4 per thread

__global__ __launch_bounds__(T3)
void ra_xform(float* __restrict__ alpha)
{
    const int gid = blockIdx.x * T3 + threadIdx.x;
    const int i4  = gid * V3;               // first float4 index
    const int b   = i4 >> 11;               // / (SS/4); pairs never straddle b

    const float M    = g_stat[2 * b];
    const float invL = g_stat[2 * b + 1];

    float4* ap = reinterpret_cast<float4*>(alpha) + i4;
    #pragma unroll
    for (int u = 0; u < V3; u++) {
        float4 s = ap[u];
        s.x = __expf(s.x - M) * invL;
        s.y = __expf(s.y - M) * invL;
        s.z = __expf(s.z - M) * invL;
        s.w = __expf(s.w - M) * invL;
        ap[u] = s;
    }
}

extern "C" void kernel_launch(void* const* d_in, const int* in_sizes, int n_in,
                              void* d_out, int out_size)
{
    const float* x = (const float*)d_in[0];   // (B, S, D) fp32
    const float* v = (const float*)d_in[1];   // (D, 1)    fp32
    float* out   = (float*)d_out;
    float* alpha = out + (size_t)BB * DD;

    ra_pass1<<<BB * CC, T1>>>(x, v, alpha);
    ra_merge<<<BB, 64>>>(out);
    ra_xform<<<(BB * SS) / (T3 * V3 * 4), T3>>>(alpha);
}

// round 17
// speedup vs baseline: 1.0918x; 1.0918x over previous
#include <cuda_runtime.h>
#include <math.h>

// RecurrentAttention: B=128, S=8192, D=64
//   scores[b,s] = sum_d x[b,s,d] * v[d]
//   alpha[b,s]  = softmax_s(scores)
//   out[b,d]    = sum_s alpha[b,s] * x[b,s,d]
// Output layout: d_out[0..B*D) = out, d_out[B*D..) = alpha.
//
//  pass1: 2048 CTAs x 256 thr, split-S C=16, online softmax.
//         NEW: batched 8-row shuffle-transpose score reduction — 9 shuffles
//         per 8 rows (was 40), serial SHFL chain per iteration cut 8x.
//  merge: 128 CTAs x 64 thr; merge 16 partials once per batch, write out,
//         store (M, invL).
//  xform: 2048 CTAs x 256 thr; alpha = exp(s - M) * invL, 1 float4/thread.

#define BB 128
#define SS 8192
#define DD 64
#define CC 16
#define ROWS_CTA (SS / CC)          // 512
#define T1 256
#define W1 (T1 / 32)                // 8 warps
#define RPW (ROWS_CTA / W1)         // 64 rows per warp
#define UU 8
#define PART_STRIDE 66              // m, l, acc[64]

__device__ float g_part[BB * CC * PART_STRIDE];
__device__ float g_stat[BB * 2];    // (M, invL) per batch

// Merge rows a (kept on lanes with bit=0) and b (kept on bit=1):
// result(l) = sum over {l, l^off} of (bit ? b : a).
__device__ __forceinline__ float ra_combine(float a, float b, int lane, int off)
{
    bool hi_lane = (lane & off) != 0;
    float keep = hi_lane ? b : a;
    float send = hi_lane ? a : b;
    return keep + __shfl_xor_sync(0xffffffffu, send, off);
}

__global__ __launch_bounds__(T1, 6)
void ra_pass1(const float* __restrict__ x,
              const float* __restrict__ v,
              float* __restrict__ alpha)   // raw scores written here
{
    __shared__ float s_scores[ROWS_CTA];   // 2 KB
    __shared__ float s_m[W1];
    __shared__ float s_l[W1];
    __shared__ float s_f[W1];
    __shared__ float s_acc[W1 * DD];       // 2 KB

    const int bx    = blockIdx.x;
    const int b     = bx >> 4;             // / CC
    const int chunk = bx & 15;
    const int tid   = threadIdx.x;
    const int w     = tid >> 5;
    const int lane  = tid & 31;

    const float v0 = v[2 * lane];
    const float v1 = v[2 * lane + 1];

    const float2* xrow =
        reinterpret_cast<const float2*>(
            x + ((size_t)b * SS + (size_t)chunk * ROWS_CTA + (size_t)w * RPW) * DD) + lane;

    float m  = -3.0e38f;
    float l  = 0.0f;
    float a0 = 0.0f, a1 = 0.0f;

    const int score_base = w * RPW;

    for (int i = 0; i < RPW; i += UU) {
        float2 xv[UU];
        #pragma unroll
        for (int u = 0; u < UU; u++)
            xv[u] = xrow[(i + u) * (DD / 2)];

        // per-lane partial dots (lane owns dims 2*lane, 2*lane+1)
        float p[UU];
        #pragma unroll
        for (int u = 0; u < UU; u++)
            p[u] = fmaf(xv[u].x, v0, xv[u].y * v1);

        // batched 8-row reduction: 9 shuffles total.
        // After this, lane l holds the full score of row i + (l & 7).
        float q0 = ra_combine(p[0], p[1], lane, 1);
        float q1 = ra_combine(p[2], p[3], lane, 1);
        float q2 = ra_combine(p[4], p[5], lane, 1);
        float q3 = ra_combine(p[6], p[7], lane, 1);
        float r0 = ra_combine(q0, q1, lane, 2);
        float r1 = ra_combine(q2, q3, lane, 2);
        float s  = ra_combine(r0, r1, lane, 4);
        s += __shfl_xor_sync(0xffffffffu, s, 8);
        s += __shfl_xor_sync(0xffffffffu, s, 16);

        // one coalesced-ish score store per 8 rows
        if (lane < UU) s_scores[score_base + i + lane] = s;

        // broadcast the 8 scores to all lanes (independent, pipelined)
        float pu[UU];
        #pragma unroll
        for (int u = 0; u < UU; u++)
            pu[u] = __shfl_sync(0xffffffffu, s, u);

        // warp-uniform online softmax update (pu identical on all lanes)
        #pragma unroll
        for (int u = 0; u < UU; u++) {
            float pv = pu[u];
            if (pv <= m) {
                float wt = __expf(pv - m);
                l += wt;
                a0 = fmaf(wt, xv[u].x, a0);
                a1 = fmaf(wt, xv[u].y, a1);
            } else {
                float corr = __expf(m - pv);
                l  = fmaf(l,  corr, 1.0f);
                a0 = fmaf(a0, corr, xv[u].x);
                a1 = fmaf(a1, corr, xv[u].y);
                m  = pv;
            }
        }
    }

    if (lane == 0) { s_m[w] = m; s_l[w] = l; }
    s_acc[w * DD + 2 * lane]     = a0;
    s_acc[w * DD + 2 * lane + 1] = a1;
    __syncthreads();

    float* part = g_part + (size_t)bx * PART_STRIDE;

    if (w == 0) {
        float mw = (lane < W1) ? s_m[lane] : -3.0e38f;
        float M  = mw;
        #pragma unroll
        for (int o = 16; o; o >>= 1) M = fmaxf(M, __shfl_xor_sync(0xffffffffu, M, o));
        float f  = __expf(mw - M);
        float lw = (lane < W1) ? s_l[lane] * f : 0.0f;
        #pragma unroll
        for (int o = 16; o; o >>= 1) lw += __shfl_xor_sync(0xffffffffu, lw, o);
        if (lane < W1) s_f[lane] = f;
        if (lane == 0) { part[0] = M; part[1] = lw; }
    }
    __syncthreads();

    if (tid < DD) {
        float acc = 0.0f;
        #pragma unroll
        for (int ww = 0; ww < W1; ww++)
            acc = fmaf(s_acc[ww * DD + tid], s_f[ww], acc);
        part[2 + tid] = acc;
    }

    if (tid < ROWS_CTA / 4) {
        float4 sc = reinterpret_cast<const float4*>(s_scores)[tid];
        reinterpret_cast<float4*>(
            alpha + (size_t)b * SS + (size_t)chunk * ROWS_CTA)[tid] = sc;
    }
}

// Merge 16 partials per batch once; write out[b,:] and (M, invL).
__global__ __launch_bounds__(64)
void ra_merge(float* __restrict__ out)
{
    __shared__ float s_f[CC];
    __shared__ float s_invL;

    const int b   = blockIdx.x;
    const int tid = threadIdx.x;
    const float* P = g_part + (size_t)(b * CC) * PART_STRIDE;

    if (tid < 32) {
        const int lane = tid;
        float mc = (lane < CC) ? P[lane * PART_STRIDE + 0] : -3.0e38f;
        float lc = (lane < CC) ? P[lane * PART_STRIDE + 1] : 0.0f;
        float M = mc;
        #pragma unroll
        for (int o = 16; o; o >>= 1) M = fmaxf(M, __shfl_xor_sync(0xffffffffu, M, o));
        float f = __expf(mc - M);
        float L = lc * f;
        #pragma unroll
        for (int o = 16; o; o >>= 1) L += __shfl_xor_sync(0xffffffffu, L, o);
        if (lane < CC) s_f[lane] = f;
        if (lane == 0) {
            float invL = 1.0f / L;
            s_invL = invL;
            g_stat[2 * b]     = M;
            g_stat[2 * b + 1] = invL;
        }
    }
    __syncthreads();

    float acc = 0.0f;
    #pragma unroll
    for (int c = 0; c < CC; c++)
        acc = fmaf(P[c * PART_STRIDE + 2 + tid], s_f[c], acc);
    out[b * DD + tid] = acc * s_invL;
}

// Pure streaming transform: alpha = exp(score - M) * invL. 1 float4/thread.
#define T3 256

__global__ __launch_bounds__(T3)
void ra_xform(float* __restrict__ alpha)
{
    const int gid = blockIdx.x * T3 + threadIdx.x;   // float4 index
    const int b   = gid >> 11;                       // / (SS/4)

    const float M    = g_stat[2 * b];
    const float invL = g_stat[2 * b + 1];

    float4* ap = reinterpret_cast<float4*>(alpha) + gid;
    float4 s = *ap;
    s.x = __expf(s.x - M) * invL;
    s.y = __expf(s.y - M) * invL;
    s.z = __expf(s.z - M) * invL;
    s.w = __expf(s.w - M) * invL;
    *ap = s;
}

extern "C" void kernel_launch(void* const* d_in, const int* in_sizes, int n_in,
                              void* d_out, int out_size)
{
    const float* x = (const float*)d_in[0];   // (B, S, D) fp32
    const float* v = (const float*)d_in[1];   // (D, 1)    fp32
    float* out   = (float*)d_out;
    float* alpha = out + (size_t)BB * DD;

    ra_pass1<<<BB * CC, T1>>>(x, v, alpha);
    ra_merge<<<BB, 64>>>(out);
    ra_xform<<<(BB * SS) / (T3 * 4), T3>>>(alpha);
}